// round 9
// baseline (speedup 1.0000x reference)
#include <cuda_runtime.h>
#include <cuda_bf16.h>
#include <cstdint>

// out = conv3x3(f(img), W)/27, f(x)=P01+P11*x+P21*x^2, zero pad.
// ldmatrix + mma.sync.m16n8k16 bf16; fp32 accuracy via 3-term bf16 split.
// Round 9: occupancy 2 (smem 101KB, <=128 regs) via CIN 2x32 chunks and
// COUT 32 per block; 64B-row tiles with (row>>1)&3 chunk-xor swizzle.

#define HW     128
#define CIN    64
#define COUT   64
#define BTILE  2048                 // [32 n][32 c] bf16, swizzled
#define ATILE  8320                 // [130 px][32 c] bf16, 64B rows
#define BOFF   0
#define AOFF   (18 * BTILE)         // 36864
#define DSMEM  (AOFF + 8 * ATILE)   // 103424

__device__ __nv_bfloat16 g_wsplit[2 * 2 * 9 * 2 * 32 * 32];  // [cc][nh][tap][part][n][c]

__device__ __forceinline__ uint32_t smem_u32(const void* p) {
    uint32_t a;
    asm("{ .reg .u64 t; cvta.to.shared.u64 t, %1; cvt.u32.u64 %0, t; }" : "=r"(a) : "l"(p));
    return a;
}
__device__ __forceinline__ void ldsm4(uint32_t* r, uint32_t a) {
    asm volatile("ldmatrix.sync.aligned.m8n8.x4.shared.b16 {%0,%1,%2,%3}, [%4];"
        : "=r"(r[0]), "=r"(r[1]), "=r"(r[2]), "=r"(r[3]) : "r"(a));
}
__device__ __forceinline__ void mma_bf16(float* d, const uint32_t* a, const uint32_t* b) {
    asm volatile("mma.sync.aligned.m16n8k16.row.col.f32.bf16.bf16.f32 "
        "{%0,%1,%2,%3}, {%4,%5,%6,%7}, {%8,%9}, {%0,%1,%2,%3};"
        : "+f"(d[0]), "+f"(d[1]), "+f"(d[2]), "+f"(d[3])
        : "r"(a[0]), "r"(a[1]), "r"(a[2]), "r"(a[3]), "r"(b[0]), "r"(b[1]));
}

__global__ void wprep_kernel(const float* __restrict__ wgt) {
    int idx = blockIdx.x * 256 + threadIdx.x;
    if (idx >= 9 * 64 * 64) return;
    int t = idx >> 12, k = (idx >> 6) & 63, c = idx & 63;
    float w = wgt[(k * 64 + c) * 9 + t];
    __nv_bfloat16 wh = __float2bfloat16(w);
    __nv_bfloat16 wl = __float2bfloat16(w - __bfloat162float(wh));
    int region = ((c >> 5) * 2 + (k >> 5)) * 18432;        // [cc][nhalf]
    int base   = region + t * 2048 + (k & 31) * 32 + (c & 31);
    g_wsplit[base]        = wh;                            // part 0
    g_wsplit[base + 1024] = wl;                            // part 1
}

__global__ __launch_bounds__(256, 2)
void conv_hmma_kernel(const float* __restrict__ img, float* __restrict__ out)
{
    extern __shared__ __align__(1024) char dsm[];
    const uint32_t sb = smem_u32(dsm);

    const int tid   = threadIdx.x, wid = tid >> 5, lane = tid & 31;
    const int bx    = blockIdx.x;
    const int nhalf = bx & 1;
    const int yb    = ((bx >> 1) & 63) * 2;
    const int n     = bx >> 7;
    const int p0    = wid * 16;
    const int px    = tid & 127, half = tid >> 7;

    const float P01 = -0.000287f, P11 = 0.266f, P21 = -0.1097f;

    // zero whole A region once (halo px rows + OOB z slots stay zero)
    for (int i = tid; i < 8 * ATILE / 4; i += 256)
        reinterpret_cast<uint32_t*>(dsm + AOFF)[i] = 0u;

    float acc[2][4][4];
    #pragma unroll
    for (int yi = 0; yi < 2; yi++)
        #pragma unroll
        for (int nt = 0; nt < 4; nt++)
            #pragma unroll
            for (int e = 0; e < 4; e++) acc[yi][nt][e] = 0.f;

    for (int cc = 0; cc < 2; cc++) {
        // ---- fill B: 18 tiles, contiguous 36KB region for (cc, nhalf) ----
        {
            const uint32_t* gw = reinterpret_cast<const uint32_t*>(g_wsplit)
                               + (cc * 2 + nhalf) * 9216;
            for (int j = tid; j < 9216; j += 256) {
                int tile = j >> 9, rem = j & 511;
                int nr = rem >> 4, cp = rem & 15;
                *reinterpret_cast<uint32_t*>(dsm + BOFF + tile * BTILE + nr * 64 +
                    (((cp >> 2) ^ ((nr >> 1) & 3)) << 4) + (cp & 3) * 4) = gw[j];
            }
        }
        // ---- fill A: 4 z rows (slot = z - (yb-1)); skip OOB (stays zero) ----
        #pragma unroll
        for (int slot = 0; slot < 4; slot++) {
            int z = yb - 1 + slot;
            if ((unsigned)z >= HW) continue;
            const float* ip = img + ((size_t)(n * CIN + cc * 32 + half * 16) * HW + z) * HW + px;
            char* a0 = dsm + AOFF + slot * 2 * ATILE;
            const int row = px + 1;
            #pragma unroll
            for (int j = 0; j < 8; j++) {
                float x0 = ip[(size_t)(2 * j) * HW * HW];
                float x1 = ip[(size_t)(2 * j + 1) * HW * HW];
                float v0 = fmaf(fmaf(P21, x0, P11), x0, P01);
                float v1 = fmaf(fmaf(P21, x1, P11), x1, P01);
                __nv_bfloat16 h0 = __float2bfloat16(v0), h1 = __float2bfloat16(v1);
                __nv_bfloat16 l0 = __float2bfloat16(v0 - __bfloat162float(h0));
                __nv_bfloat16 l1 = __float2bfloat16(v1 - __bfloat162float(h1));
                uint32_t hp = ((uint32_t)__bfloat16_as_ushort(h1) << 16) | __bfloat16_as_ushort(h0);
                uint32_t lp = ((uint32_t)__bfloat16_as_ushort(l1) << 16) | __bfloat16_as_ushort(l0);
                int c2  = half * 16 + 2 * j;
                int off = row * 64 + (((c2 >> 3) ^ ((row >> 1) & 3)) << 4) + (c2 & 7) * 2;
                *reinterpret_cast<uint32_t*>(a0 + off)         = hp;
                *reinterpret_cast<uint32_t*>(a0 + ATILE + off) = lp;
            }
        }
        __syncthreads();

        // ---- compute: 9 taps ----
        #pragma unroll
        for (int r = 0; r < 3; r++) {
            #pragma unroll
            for (int s = 0; s < 3; s++) {
                // A fragments: af[yi][part][kc]
                const int rowA = p0 + s + (lane & 7) + ((lane >> 3) & 1) * 8;
                const int chA  = lane >> 4;
                uint32_t af[2][2][2][4];
                #pragma unroll
                for (int yi = 0; yi < 2; yi++)
                    #pragma unroll
                    for (int part = 0; part < 2; part++) {
                        uint32_t ab = sb + AOFF + ((r + yi) * 2 + part) * ATILE + rowA * 64;
                        #pragma unroll
                        for (int kc = 0; kc < 2; kc++)
                            ldsm4(af[yi][part][kc],
                                  ab + ((((kc * 2 + chA)) ^ ((rowA >> 1) & 3)) << 4));
                    }
                // B fragments: bf[part][kc][ntp] (each covers 2 n8-tiles)
                const int chB = (lane >> 3) & 1;
                uint32_t bf[2][2][2][4];
                #pragma unroll
                for (int part = 0; part < 2; part++) {
                    uint32_t bb = sb + BOFF + ((r * 3 + s) * 2 + part) * BTILE;
                    #pragma unroll
                    for (int kc = 0; kc < 2; kc++)
                        #pragma unroll
                        for (int ntp = 0; ntp < 2; ntp++) {
                            int nr = ntp * 16 + (lane >> 4) * 8 + (lane & 7);
                            ldsm4(bf[part][kc][ntp], bb + nr * 64 +
                                  (((kc * 2 + chB) ^ ((nr >> 1) & 3)) << 4));
                        }
                }
                // MMAs: per kc, per term, 8 distinct accumulators before reuse
                #pragma unroll
                for (int kc = 0; kc < 2; kc++)
                    #pragma unroll
                    for (int term = 0; term < 3; term++) {
                        const int ap = (term == 1) ? 1 : 0;
                        const int bp = (term == 2) ? 1 : 0;
                        #pragma unroll
                        for (int yi = 0; yi < 2; yi++)
                            #pragma unroll
                            for (int ntp = 0; ntp < 2; ntp++) {
                                mma_bf16(acc[yi][ntp * 2],     af[yi][ap][kc], bf[bp][kc][ntp]);
                                mma_bf16(acc[yi][ntp * 2 + 1], af[yi][ap][kc], bf[bp][kc][ntp] + 2);
                            }
                    }
            }
        }
        __syncthreads();
    }

    // ---- epilogue: scale by 1/27 ----
    const float sc = 1.f / 27.f;
    #pragma unroll
    for (int yi = 0; yi < 2; yi++) {
        const int y = yb + yi;
        #pragma unroll
        for (int nt = 0; nt < 4; nt++) {
            int kout = nhalf * 32 + nt * 8 + 2 * (lane & 3);
            int pxo  = p0 + (lane >> 2);
            float* o = out + ((size_t)(n * COUT + kout) * HW + y) * HW;
            o[pxo]               = acc[yi][nt][0] * sc;
            o[HW * HW + pxo]     = acc[yi][nt][1] * sc;
            o[pxo + 8]           = acc[yi][nt][2] * sc;
            o[HW * HW + pxo + 8] = acc[yi][nt][3] * sc;
        }
    }
}

extern "C" void kernel_launch(void* const* d_in, const int* in_sizes, int n_in,
                              void* d_out, int out_size)
{
    const float* img = (const float*)d_in[0];
    const float* wgt = (const float*)d_in[1];
    float* out = (float*)d_out;

    cudaFuncSetAttribute(conv_hmma_kernel,
                         cudaFuncAttributeMaxDynamicSharedMemorySize, DSMEM);

    int N = in_sizes[0] / (CIN * HW * HW);   // 16
    wprep_kernel<<<144, 256>>>(wgt);
    conv_hmma_kernel<<<N * 128, 256, DSMEM>>>(img, out);
}

// round 10
// speedup vs baseline: 1.6459x; 1.6459x over previous
#include <cuda_runtime.h>
#include <cuda_bf16.h>
#include <cstdint>

// out = conv3x3(f(img), W)/27, f(x)=P01+P11*x+P21*x^2, zero pad.
// ldmatrix + mma.sync.m16n8k16 bf16; fp32 accuracy via 3-term bf16 split.
// Round 10: round-8 shape + cp.async B fills (pre-swizzled weight images),
// staged A fills (LDG early / STS late), B-fragment nt2 double-buffering.

#define HW     128
#define CIN    64
#define COUT   64
#define BTILE  8192                 // [64 n][64 k] bf16, swizzled image
#define ATILE  16640                // [130 px][64 c] bf16 (128 B rows)
#define BGRP   (6 * BTILE)          // tap-row group: 3 s x 2 parts
#define BOFF   0
#define AOFF   (2 * BGRP)           // 98304
#define DSMEM  (AOFF + 6 * ATILE)   // 198144

__device__ __align__(16) char g_wimg[18 * BTILE];   // swizzled smem images

__device__ __forceinline__ uint32_t smem_u32(const void* p) {
    uint32_t a;
    asm("{ .reg .u64 t; cvta.to.shared.u64 t, %1; cvt.u32.u64 %0, t; }" : "=r"(a) : "l"(p));
    return a;
}
__device__ __forceinline__ void ldsm4(uint32_t* r, uint32_t a) {
    asm volatile("ldmatrix.sync.aligned.m8n8.x4.shared.b16 {%0,%1,%2,%3}, [%4];"
        : "=r"(r[0]), "=r"(r[1]), "=r"(r[2]), "=r"(r[3]) : "r"(a));
}
__device__ __forceinline__ void mma_bf16(float* d, const uint32_t* a, const uint32_t* b) {
    asm volatile("mma.sync.aligned.m16n8k16.row.col.f32.bf16.bf16.f32 "
        "{%0,%1,%2,%3}, {%4,%5,%6,%7}, {%8,%9}, {%0,%1,%2,%3};"
        : "+f"(d[0]), "+f"(d[1]), "+f"(d[2]), "+f"(d[3])
        : "r"(a[0]), "r"(a[1]), "r"(a[2]), "r"(a[3]), "r"(b[0]), "r"(b[1]));
}
__device__ __forceinline__ void cp16(uint32_t saddr, const void* g) {
    asm volatile("cp.async.cg.shared.global [%0], [%1], 16;"
        :: "r"(saddr), "l"(__cvta_generic_to_global(g)) : "memory");
}
#define CP_COMMIT() asm volatile("cp.async.commit_group;" ::: "memory")
#define CP_WAIT0()  asm volatile("cp.async.wait_group 0;" ::: "memory")

__global__ void wprep_kernel(const float* __restrict__ wgt) {
    int idx = blockIdx.x * 256 + threadIdx.x;
    if (idx >= 9 * 64 * 64) return;
    int t = idx >> 12, k = (idx >> 6) & 63, c = idx & 63;
    float w = wgt[(k * 64 + c) * 9 + t];
    __nv_bfloat16 wh = __float2bfloat16(w);
    __nv_bfloat16 wl = __float2bfloat16(w - __bfloat162float(wh));
    // byte offset inside the swizzled tile image (matches compute-side ldsm addressing)
    int off = k * 128 + (((c >> 3) ^ (k & 7)) << 4) + (((c >> 1) & 3) << 2) + ((c & 1) << 1);
    *reinterpret_cast<__nv_bfloat16*>(g_wimg + (t * 2 + 0) * BTILE + off) = wh;
    *reinterpret_cast<__nv_bfloat16*>(g_wimg + (t * 2 + 1) * BTILE + off) = wl;
}

__global__ __launch_bounds__(256, 1)
void conv_hmma_kernel(const float* __restrict__ img, float* __restrict__ out)
{
    extern __shared__ __align__(1024) char dsm[];
    const uint32_t sb = smem_u32(dsm);

    const int tid  = threadIdx.x, wid = tid >> 5, lane = tid & 31;
    const int n    = blockIdx.x >> 6;
    const int yb   = (blockIdx.x & 63) * 2;
    const int p0   = wid * 16;
    const int px   = tid & 127, chalf = tid >> 7;

    const float P01 = -0.000287f, P11 = 0.266f, P21 = -0.1097f;

    // async copy of tap-row group g into B buffer bbuf (pre-swizzled image)
    auto fillB_async = [&](int g, int bbuf) {
        const char* src = g_wimg + g * BGRP;
        uint32_t dst = sb + BOFF + bbuf * BGRP;
        #pragma unroll
        for (int j = 0; j < 12; j++) {
            int o = (tid + j * 256) * 16;
            cp16(dst + o, src + o);
        }
        CP_COMMIT();
    };
    // direct fill (prologue): row z -> slot (poly + split + swizzle), zeros if OOB
    auto fillA = [&](int z, int slot) {
        char* a0 = dsm + AOFF + slot * 2 * ATILE;
        if ((unsigned)z < HW) {
            const float* ip = img + ((size_t)(n * CIN + chalf * 32) * HW + z) * HW + px;
            const int rs = px + 1;
            #pragma unroll
            for (int i = 0; i < 16; i++) {
                int c2 = chalf * 32 + 2 * i;
                float x0 = ip[(size_t)(2 * i) * HW * HW];
                float x1 = ip[(size_t)(2 * i + 1) * HW * HW];
                float v0 = fmaf(fmaf(P21, x0, P11), x0, P01);
                float v1 = fmaf(fmaf(P21, x1, P11), x1, P01);
                __nv_bfloat16 h0 = __float2bfloat16(v0), h1 = __float2bfloat16(v1);
                __nv_bfloat16 l0 = __float2bfloat16(v0 - __bfloat162float(h0));
                __nv_bfloat16 l1 = __float2bfloat16(v1 - __bfloat162float(h1));
                uint32_t hp = ((uint32_t)__bfloat16_as_ushort(h1) << 16) | __bfloat16_as_ushort(h0);
                uint32_t lp = ((uint32_t)__bfloat16_as_ushort(l1) << 16) | __bfloat16_as_ushort(l0);
                int off = rs * 128 + ((((c2 >> 3) ^ (rs & 7))) << 4) + (c2 & 7) * 2;
                *reinterpret_cast<uint32_t*>(a0 + off)         = hp;
                *reinterpret_cast<uint32_t*>(a0 + ATILE + off) = lp;
            }
        } else {
            for (int i = tid; i < 2 * ATILE / 4; i += 256)
                reinterpret_cast<uint32_t*>(a0)[i] = 0u;
        }
    };

    // prologue: halo rows of all slots, first two A rows, B group 0 (async)
    fillB_async(0, 0);
    for (int j = tid; j < 3 * 2 * 2 * 32; j += 256) {
        int slot = j >> 7, rem = j & 127;
        int part = rem >> 6, rw = (rem >> 5) & 1, col = rem & 31;
        *reinterpret_cast<uint32_t*>(dsm + AOFF + (slot * 2 + part) * ATILE +
                                     (rw ? 129 : 0) * 128 + col * 4) = 0u;
    }
    fillA(yb - 1, 0);
    fillA(yb,     1);
    CP_WAIT0();
    __syncthreads();

    float acc[2][8][4];
    #pragma unroll
    for (int yi = 0; yi < 2; yi++)
        #pragma unroll
        for (int nt = 0; nt < 8; nt++)
            #pragma unroll
            for (int e = 0; e < 4; e++) acc[yi][nt][e] = 0.f;

    for (int r = 0; r < 3; r++) {
        const uint32_t abase0 = sb + AOFF + (r % 3) * 2 * ATILE;        // z = yb-1+r
        const uint32_t abase1 = sb + AOFF + ((r + 1) % 3) * 2 * ATILE;  // z = yb+r
        const uint32_t bbase  = sb + BOFF + (r & 1) * BGRP;

        // ---- start async work for next r: B copy + staged A LDGs ----
        const int  zn   = yb + r + 1;
        const bool more = (r < 2);
        float stg[32];
        if (more) {
            fillB_async(r + 1, (r + 1) & 1);
            if ((unsigned)zn < HW) {
                const float* ip = img + ((size_t)(n * CIN + chalf * 32) * HW + zn) * HW + px;
                #pragma unroll
                for (int i = 0; i < 32; i++) stg[i] = ip[(size_t)i * HW * HW];
            }
        }

        // ---- compute: 3 s taps, B fragments double-buffered over nt2 ----
        #pragma unroll
        for (int s = 0; s < 3; s++) {
            uint32_t af[2][2][4][4];
            const int rowA = p0 + s + (lane & 7) + ((lane >> 3) & 1) * 8;
            const int chA  = lane >> 4;
            #pragma unroll
            for (int yi = 0; yi < 2; yi++) {
                uint32_t ay = (yi ? abase1 : abase0) + rowA * 128;
                #pragma unroll
                for (int part = 0; part < 2; part++)
                    #pragma unroll
                    for (int kc = 0; kc < 4; kc++) {
                        int ch = 2 * kc + chA;
                        ldsm4(af[yi][part][kc], ay + part * ATILE + ((ch ^ (rowA & 7)) << 4));
                    }
            }
            const uint32_t btile = bbase + s * 2 * BTILE;
            const int chB = (lane >> 3) & 1;
            uint32_t bf[2][2][4][4];   // [pipe][part][kc][4]
            auto loadB = [&](uint32_t (*dst)[4][4], int nt2) {
                const int nrow = (nt2 * 2 + (lane >> 4)) * 8 + (lane & 7);
                #pragma unroll
                for (int part = 0; part < 2; part++)
                    #pragma unroll
                    for (int kc = 0; kc < 4; kc++) {
                        int ch = 2 * kc + chB;
                        ldsm4(dst[part][kc],
                              btile + part * BTILE + nrow * 128 + ((ch ^ (nrow & 7)) << 4));
                    }
            };
            loadB(bf[0], 0);
            #pragma unroll
            for (int nt2 = 0; nt2 < 4; nt2++) {
                if (nt2 < 3) loadB(bf[(nt2 + 1) & 1], nt2 + 1);
                uint32_t (*b)[4][4] = bf[nt2 & 1];
                #pragma unroll
                for (int kc = 0; kc < 4; kc++)
                    #pragma unroll
                    for (int yi = 0; yi < 2; yi++) {
                        mma_bf16(acc[yi][nt2 * 2],     af[yi][0][kc], b[0][kc]);      // hh
                        mma_bf16(acc[yi][nt2 * 2 + 1], af[yi][0][kc], b[0][kc] + 2);
                        mma_bf16(acc[yi][nt2 * 2],     af[yi][1][kc], b[0][kc]);      // lh
                        mma_bf16(acc[yi][nt2 * 2 + 1], af[yi][1][kc], b[0][kc] + 2);
                        mma_bf16(acc[yi][nt2 * 2],     af[yi][0][kc], b[1][kc]);      // hl
                        mma_bf16(acc[yi][nt2 * 2 + 1], af[yi][0][kc], b[1][kc] + 2);
                    }
            }
        }

        // ---- finish staged A fill (slot (r+2)%3), drain B copy, sync ----
        if (more) {
            char* a0 = dsm + AOFF + ((r + 2) % 3) * 2 * ATILE;
            const int rs = px + 1;
            const bool ok = (unsigned)zn < HW;
            #pragma unroll
            for (int i = 0; i < 16; i++) {
                int c2 = chalf * 32 + 2 * i;
                uint32_t hp = 0u, lp = 0u;
                if (ok) {
                    float v0 = fmaf(fmaf(P21, stg[2*i],   P11), stg[2*i],   P01);
                    float v1 = fmaf(fmaf(P21, stg[2*i+1], P11), stg[2*i+1], P01);
                    __nv_bfloat16 h0 = __float2bfloat16(v0), h1 = __float2bfloat16(v1);
                    __nv_bfloat16 l0 = __float2bfloat16(v0 - __bfloat162float(h0));
                    __nv_bfloat16 l1 = __float2bfloat16(v1 - __bfloat162float(h1));
                    hp = ((uint32_t)__bfloat16_as_ushort(h1) << 16) | __bfloat16_as_ushort(h0);
                    lp = ((uint32_t)__bfloat16_as_ushort(l1) << 16) | __bfloat16_as_ushort(l0);
                }
                int off = rs * 128 + ((((c2 >> 3) ^ (rs & 7))) << 4) + (c2 & 7) * 2;
                *reinterpret_cast<uint32_t*>(a0 + off)         = hp;
                *reinterpret_cast<uint32_t*>(a0 + ATILE + off) = lp;
            }
            CP_WAIT0();
        }
        __syncthreads();
    }

    // ---- epilogue: scale by 1/27 ----
    const float sc = 1.f / 27.f;
    #pragma unroll
    for (int yi = 0; yi < 2; yi++) {
        const int y = yb + yi;
        #pragma unroll
        for (int nt = 0; nt < 8; nt++) {
            int kout = nt * 8 + 2 * (lane & 3);
            int pxo  = p0 + (lane >> 2);
            float* o = out + ((size_t)(n * COUT + kout) * HW + y) * HW;
            o[pxo]               = acc[yi][nt][0] * sc;
            o[HW * HW + pxo]     = acc[yi][nt][1] * sc;
            o[pxo + 8]           = acc[yi][nt][2] * sc;
            o[HW * HW + pxo + 8] = acc[yi][nt][3] * sc;
        }
    }
}

extern "C" void kernel_launch(void* const* d_in, const int* in_sizes, int n_in,
                              void* d_out, int out_size)
{
    const float* img = (const float*)d_in[0];
    const float* wgt = (const float*)d_in[1];
    float* out = (float*)d_out;

    cudaFuncSetAttribute(conv_hmma_kernel,
                         cudaFuncAttributeMaxDynamicSharedMemorySize, DSMEM);

    int N = in_sizes[0] / (CIN * HW * HW);   // 16
    wprep_kernel<<<144, 256>>>(wgt);
    conv_hmma_kernel<<<N * 64, 256, DSMEM>>>(img, out);
}